// round 14
// baseline (speedup 1.0000x reference)
#include <cuda_runtime.h>

// Problem dims
#define BDIM 8
#define MDIM 4
#define TLEN 2048
#define EDIM 768
#define PDIM 256
#define KDIM 64
#define VDIM 64
#define HDIM 128
#define GDIM 384   /* 3*H */
#define CDIM 384   /* P + H */
#define HIDD 192
#define NEXPD 16
#define NTOK (BDIM*MDIM*TLEN)   /* 65536 */
#define NSEQ (BDIM*MDIM)        /* 32 */

// ---------------- scratch (device globals; no allocation allowed) ----------------
__device__ float g_proc[(size_t)NTOK * PDIM];   // 64 MB: relu(te @ tp_w^T + b)
__device__ float g_rs[(size_t)NTOK * 2];        // (rbar, sbar) per token
__device__ float g_rus[(size_t)NTOK * HDIM];    // GRU outputs
__device__ float g_hid[(size_t)NTOK * HIDD];    // MLP hidden (partial, then final)
__device__ float g_pa[PDIM], g_pb[PDIM], g_pc[PDIM];
__device__ float g_wu[GDIM], g_wr[GDIM], g_wsv[GDIM], g_w0[GDIM];
__device__ float g_cabc[3];

__constant__ int c_others[4][3] = {{1,2,3},{0,2,3},{0,1,3},{0,1,2}};

// ---------------- f32x2 packed-FMA helpers (sm_100+/sm_103a) ----------------
__device__ __forceinline__ unsigned long long pack2(float lo, float hi) {
    unsigned long long r;
    asm("mov.b64 %0, {%1, %2};" : "=l"(r) : "f"(lo), "f"(hi));
    return r;
}
__device__ __forceinline__ float2 unpack2(unsigned long long v) {
    float2 r;
    asm("mov.b64 {%0, %1}, %2;" : "=f"(r.x), "=f"(r.y) : "l"(v));
    return r;
}
__device__ __forceinline__ void fma2(unsigned long long& d, unsigned long long a, unsigned long long b) {
    asm("fma.rn.f32x2 %0, %1, %2, %0;" : "+l"(d) : "l"(a), "l"(b));
}

__device__ __forceinline__ float sigmoidf_(float x) { return 1.f / (1.f + __expf(-x)); }
__device__ __forceinline__ float tanhf_(float x)    { return 1.f - 2.f / (__expf(2.f * x) + 1.f); }

// ---------------- precompute folded small weights ----------------
__global__ void k_pre(const float* __restrict__ qw, const float* __restrict__ qb,
                      const float* __restrict__ kw, const float* __restrict__ kb,
                      const float* __restrict__ vw, const float* __restrict__ vb,
                      const float* __restrict__ wih, const float* __restrict__ bih) {
    int j = threadIdx.x;
    if (j < PDIM) {
        float a = 0.f, b = 0.f, c = 0.f;
        for (int k = 0; k < KDIM; k++) {
            float q = qw[k * PDIM + j];
            a = fmaf(q, kw[2 * k], a);
            b = fmaf(q, kw[2 * k + 1], b);
            c = fmaf(q, kb[k], c);
        }
        g_pa[j] = a; g_pb[j] = b; g_pc[j] = c;
    }
    if (j < GDIM) {
        float wr = 0.f, ws = 0.f, w0 = 0.f;
        for (int v = 0; v < VDIM; v++) {
            float w = wih[j * (1 + VDIM) + 1 + v];
            wr = fmaf(w, vw[2 * v], wr);
            ws = fmaf(w, vw[2 * v + 1], ws);
            w0 = fmaf(w, vb[v], w0);
        }
        g_wu[j] = wih[j * (1 + VDIM)];
        g_wr[j] = wr; g_wsv[j] = ws; g_w0[j] = w0 + bih[j];
    }
    if (j == 0) {
        float a = 0.f, b = 0.f, c = 0.f;
        for (int k = 0; k < KDIM; k++) {
            a = fmaf(qb[k], kw[2 * k], a);
            b = fmaf(qb[k], kw[2 * k + 1], b);
            c = fmaf(qb[k], kb[k], c);
        }
        g_cabc[0] = a; g_cabc[1] = b; g_cabc[2] = c;
    }
}

// ---------------- GEMM1: g_proc = relu(te[NTOK,768] @ tp_w[256,768]^T + b) ----------------
// Tile 128x128x16, 256 threads, 8x8 microtile via f32x2.
__global__ __launch_bounds__(256, 2) void k_gemm1(const float* __restrict__ A,
                                                  const float* __restrict__ W,
                                                  const float* __restrict__ bias) {
    __shared__ float As[16][132];
    __shared__ float Ws[16][132];
    const int bi = blockIdx.x, bj = blockIdx.y;
    const int tid = threadIdx.x;
    const int tx = tid & 15, ty = tid >> 4;
    const int row0 = bi * 128, col0 = bj * 128;

    unsigned long long acc[8][4];
#pragma unroll
    for (int i = 0; i < 8; i++)
#pragma unroll
        for (int j = 0; j < 4; j++) acc[i][j] = 0ull;

    for (int ks = 0; ks < EDIM / 16; ks++) {
#pragma unroll
        for (int p = 0; p < 2; p++) {
            int idx = tid + p * 256;
            int r = idx >> 2;
            int kq = (idx & 3) << 2;
            float4 av = *(const float4*)&A[(size_t)(row0 + r) * EDIM + ks * 16 + kq];
            As[kq + 0][r] = av.x; As[kq + 1][r] = av.y; As[kq + 2][r] = av.z; As[kq + 3][r] = av.w;
            float4 wv = *(const float4*)&W[(size_t)(col0 + r) * EDIM + ks * 16 + kq];
            Ws[kq + 0][r] = wv.x; Ws[kq + 1][r] = wv.y; Ws[kq + 2][r] = wv.z; Ws[kq + 3][r] = wv.w;
        }
        __syncthreads();
#pragma unroll
        for (int kk = 0; kk < 16; kk++) {
            float4 a0 = *(const float4*)&As[kk][ty * 8];
            float4 a1 = *(const float4*)&As[kk][ty * 8 + 4];
            ulonglong2 wv0 = *(const ulonglong2*)&Ws[kk][tx * 8];
            ulonglong2 wv1 = *(const ulonglong2*)&Ws[kk][tx * 8 + 4];
            float ar[8] = {a0.x, a0.y, a0.z, a0.w, a1.x, a1.y, a1.z, a1.w};
#pragma unroll
            for (int i = 0; i < 8; i++) {
                unsigned long long ad = pack2(ar[i], ar[i]);
                fma2(acc[i][0], ad, wv0.x);
                fma2(acc[i][1], ad, wv0.y);
                fma2(acc[i][2], ad, wv1.x);
                fma2(acc[i][3], ad, wv1.y);
            }
        }
        __syncthreads();
    }
    const int crow = row0 + ty * 8;
    const int ccol = col0 + tx * 8;
    float bb[8];
#pragma unroll
    for (int j = 0; j < 8; j++) bb[j] = bias[ccol + j];
#pragma unroll
    for (int i = 0; i < 8; i++) {
        float2 p0 = unpack2(acc[i][0]), p1 = unpack2(acc[i][1]);
        float2 p2 = unpack2(acc[i][2]), p3 = unpack2(acc[i][3]);
        float4 v0 = make_float4(fmaxf(p0.x + bb[0], 0.f), fmaxf(p0.y + bb[1], 0.f),
                                fmaxf(p1.x + bb[2], 0.f), fmaxf(p1.y + bb[3], 0.f));
        float4 v1 = make_float4(fmaxf(p2.x + bb[4], 0.f), fmaxf(p2.y + bb[5], 0.f),
                                fmaxf(p3.x + bb[6], 0.f), fmaxf(p3.y + bb[7], 0.f));
        *(float4*)&g_proc[(size_t)(crow + i) * PDIM + ccol]     = v0;
        *(float4*)&g_proc[(size_t)(crow + i) * PDIM + ccol + 4] = v1;
    }
}

// ---------------- attention scalars: per token -> (rbar, sbar) ----------------
__global__ __launch_bounds__(256) void k_attn(const float* __restrict__ R, const float* __restrict__ S) {
    __shared__ float spa[PDIM], spb[PDIM], spc[PDIM];
    int tid = threadIdx.x;
    if (tid < PDIM) { spa[tid] = g_pa[tid]; spb[tid] = g_pb[tid]; spc[tid] = g_pc[tid]; }
    __syncthreads();
    int warp = tid >> 5, lane = tid & 31;
    size_t i = (size_t)blockIdx.x * 8 + warp;
    const float* pr = &g_proc[i * PDIM];
    float a = 0.f, b = 0.f, c = 0.f;
#pragma unroll
    for (int q = 0; q < 8; q++) {
        int p = lane + 32 * q;
        float x = pr[p];
        a = fmaf(x, spa[p], a);
        b = fmaf(x, spb[p], b);
        c = fmaf(x, spc[p], c);
    }
#pragma unroll
    for (int d = 16; d > 0; d >>= 1) {
        a += __shfl_xor_sync(0xffffffffu, a, d);
        b += __shfl_xor_sync(0xffffffffu, b, d);
        c += __shfl_xor_sync(0xffffffffu, c, d);
    }
    if (lane == 0) {
        a += g_cabc[0]; b += g_cabc[1]; c += g_cabc[2];
        int t = (int)(i & (TLEN - 1));
        int bm = (int)(i >> 11);
        int m = bm & 3, bb = bm >> 2;
        float r[3], s[3], sc[3];
#pragma unroll
        for (int n = 0; n < 3; n++) {
            int o = c_others[m][n];
            size_t off = (((size_t)bb * 4 + m) * 4 + o) * TLEN + t;
            r[n] = R[off]; s[n] = S[off];
            sc[n] = (fmaf(a, r[n], fmaf(b, s[n], c))) * 0.125f;
        }
        float mx = fmaxf(sc[0], fmaxf(sc[1], sc[2]));
        float e0 = __expf(sc[0] - mx), e1 = __expf(sc[1] - mx), e2 = __expf(sc[2] - mx);
        float inv = __fdividef(1.f, e0 + e1 + e2);
        float rb = (e0 * r[0] + e1 * r[1] + e2 * r[2]) * inv;
        float sb = (e0 * s[0] + e1 * s[1] + e2 * s[2]) * inv;
        g_rs[i * 2 + 0] = rb;
        g_rs[i * 2 + 1] = sb;
    }
}

// ---------------- fused GRU (v3) + MLP1a, CTA-specialized ----------------
// blocks 0..31: GRU, one sequence each (768 thr, half-row split, ~80 regs, 24 warps).
// blocks 32..543: MLP1a: g_hid[128x192 tile] = proc @ W1a^T + b1   (no relu yet).
// MLP1a (~115 us over 116 SMs) hides entirely inside the GRU shadow.
#define GRU_THREADS 768
#define MLPA_BLOCKS (NTOK / 128)   /* 512 */

struct GruSm {
    float  h[HDIM];
    float2 p[GDIM];
    float  xn[HDIM];
    float  u[TLEN];
    float  rs[2 * TLEN];
    float  cw[5][GDIM];
};
struct MlpSm {
    float As[16][132];
    float Ws[16][196];
};
union GruMlpSm { GruSm gru; MlpSm mlp; };

__global__ __launch_bounds__(GRU_THREADS, 1) void k_gru_mlp1a(
        const float* __restrict__ U,
        const float* __restrict__ whh,
        const float* __restrict__ bhh,
        const float* __restrict__ w1,
        const float* __restrict__ b1) {
    __shared__ GruMlpSm sm;
    const int tid = threadIdx.x;

    if (blockIdx.x < NSEQ) {
        // ================= GRU branch (audited v3) =================
        float*  sh_h  = sm.gru.h;
        float2* sh_p  = sm.gru.p;
        float*  sh_xn = sm.gru.xn;
        float*  sh_u  = sm.gru.u;
        float*  sh_rs = sm.gru.rs;
        float (*sh_cw)[GDIM] = sm.gru.cw;

        const int half = (tid >= GDIM) ? 1 : 0;
        const int row  = tid - half * GDIM;
        const int s    = blockIdx.x;

        unsigned long long w2[32];
        {
            const float4* wrow = (const float4*)(whh + (size_t)row * HDIM + half * 64);
#pragma unroll
            for (int q = 0; q < 16; q++) {
                float4 f = wrow[q];
                w2[2 * q]     = pack2(f.x, f.y);
                w2[2 * q + 1] = pack2(f.z, f.w);
            }
        }
        for (int i = tid; i < GDIM; i += GRU_THREADS) {
            sh_cw[0][i] = g_wu[i]; sh_cw[1][i] = g_wr[i]; sh_cw[2][i] = g_wsv[i];
            sh_cw[3][i] = g_w0[i]; sh_cw[4][i] = bhh[i];
        }
        for (int i = tid; i < TLEN; i += GRU_THREADS)     sh_u[i]  = U[(size_t)s * TLEN + i];
        for (int i = tid; i < 2 * TLEN; i += GRU_THREADS) sh_rs[i] = g_rs[(size_t)s * (2 * TLEN) + i];
        float hold = 0.f;
        if (tid < HDIM) sh_h[tid] = 0.f;
        __syncthreads();

        const ulonglong2* hbase = ((const ulonglong2*)sh_h) + half * 16;
        float* rus_seq = &g_rus[(size_t)s * TLEN * HDIM];

        for (int t = 0; t < TLEN; t++) {
            unsigned long long a0 = 0ull, a1 = 0ull;
#pragma unroll
            for (int q = 0; q < 16; q++) {
                ulonglong2 hv = hbase[q];
                fma2(a0, w2[2 * q],     hv.x);
                fma2(a1, w2[2 * q + 1], hv.y);
            }
            float2 f0 = unpack2(a0), f1 = unpack2(a1);
            float part = (f0.x + f0.y) + (f1.x + f1.y);
            if (!half) {
                float u = sh_u[t], rb = sh_rs[2 * t], sb = sh_rs[2 * t + 1];
                float xp = fmaf(u, sh_cw[0][row],
                            fmaf(rb, sh_cw[1][row],
                            fmaf(sb, sh_cw[2][row], sh_cw[3][row])));
                part += sh_cw[4][row];
                if (row < 2 * HDIM) part += xp;
                else                sh_xn[row - 2 * HDIM] = xp;
            }
            ((float*)&sh_p[row])[half] = part;
            __syncthreads();
            if (tid < HDIM) {
                float2 pr = sh_p[tid];
                float2 pz = sh_p[HDIM + tid];
                float2 pn = sh_p[2 * HDIM + tid];
                float r = sigmoidf_(pr.x + pr.y);
                float z = sigmoidf_(pz.x + pz.y);
                float n = tanhf_(fmaf(r, pn.x + pn.y, sh_xn[tid]));
                hold = fmaf(z, hold - n, n);
                sh_h[tid] = hold;
                rus_seq[(size_t)t * HDIM + tid] = hold;
            }
            __syncthreads();
        }
    } else {
        // ================= MLP1a branch =================
        // g_hid[row0..row0+128, 0..192] = g_proc[rows,0:256] @ w1[:,0:256]^T + b1
        float (*As)[132] = sm.mlp.As;
        float (*Ws)[196] = sm.mlp.Ws;
        const int bid  = blockIdx.x - NSEQ;       // 0..511
        const int row0 = bid * 128;
        const int ty = tid >> 5, tx = tid & 31;   // compute threads: tid<512 -> ty 0..15

        unsigned long long acc[8][3];
#pragma unroll
        for (int i = 0; i < 8; i++)
#pragma unroll
            for (int j = 0; j < 3; j++) acc[i][j] = 0ull;

        for (int ks = 0; ks < PDIM / 16; ks++) {   // 16 k-slices of 16
            if (tid < 512) {                        // A: 128 rows x 16 k = 512 float4
                int r  = tid >> 2;
                int kq = (tid & 3) << 2;
                float4 av = *(const float4*)&g_proc[(size_t)(row0 + r) * PDIM + ks * 16 + kq];
                As[kq + 0][r] = av.x; As[kq + 1][r] = av.y; As[kq + 2][r] = av.z; As[kq + 3][r] = av.w;
            }
            {                                       // W: 192 rows x 16 k = 768 float4, one per thread
                int c  = tid >> 2;                  // 0..191
                int kq = (tid & 3) << 2;
                float4 wv = *(const float4*)&w1[(size_t)c * CDIM + ks * 16 + kq];
                Ws[kq + 0][c] = wv.x; Ws[kq + 1][c] = wv.y; Ws[kq + 2][c] = wv.z; Ws[kq + 3][c] = wv.w;
            }
            __syncthreads();
            if (tid < 512) {
#pragma unroll
                for (int kk = 0; kk < 16; kk++) {
                    float4 a0 = *(const float4*)&As[kk][ty * 8];
                    float4 a1 = *(const float4*)&As[kk][ty * 8 + 4];
                    const unsigned long long* wp = (const unsigned long long*)&Ws[kk][tx * 6];
                    unsigned long long wv0 = wp[0], wv1 = wp[1], wv2 = wp[2];
                    float ar[8] = {a0.x, a0.y, a0.z, a0.w, a1.x, a1.y, a1.z, a1.w};
#pragma unroll
                    for (int i = 0; i < 8; i++) {
                        unsigned long long ad = pack2(ar[i], ar[i]);
                        fma2(acc[i][0], ad, wv0);
                        fma2(acc[i][1], ad, wv1);
                        fma2(acc[i][2], ad, wv2);
                    }
                }
            }
            __syncthreads();
        }
        if (tid < 512) {
            const int crow = row0 + ty * 8;
            const int ccol = tx * 6;
            float bb[6];
#pragma unroll
            for (int j = 0; j < 6; j++) bb[j] = b1[ccol + j];
#pragma unroll
            for (int i = 0; i < 8; i++) {
                float2 p0 = unpack2(acc[i][0]), p1 = unpack2(acc[i][1]), p2 = unpack2(acc[i][2]);
                size_t base = (size_t)(crow + i) * HIDD + ccol;
                *(float2*)&g_hid[base]     = make_float2(p0.x + bb[0], p0.y + bb[1]);
                *(float2*)&g_hid[base + 2] = make_float2(p1.x + bb[2], p1.y + bb[3]);
                *(float2*)&g_hid[base + 4] = make_float2(p2.x + bb[4], p2.y + bb[5]);
            }
        }
    }
}

// ---------------- MLP1b: g_hid = relu(g_hid_partial + rus @ W1b^T) ----------------
// Tile 128x96x16, 256 threads, 8x6 microtile; K = 128 (rus part only).
__global__ __launch_bounds__(256, 2) void k_mlp1b(const float* __restrict__ W) {
    __shared__ float As[16][132];
    __shared__ float Ws[16][100];
    const int bi = blockIdx.x, bj = blockIdx.y;
    const int tid = threadIdx.x;
    const int tx = tid & 15, ty = tid >> 4;
    const int row0 = bi * 128, col0 = bj * 96;

    unsigned long long acc[8][3];
#pragma unroll
    for (int i = 0; i < 8; i++)
#pragma unroll
        for (int j = 0; j < 3; j++) acc[i][j] = 0ull;

    for (int ks = 0; ks < HDIM / 16; ks++) {   // 8 k-slices over the rus 128 dims
#pragma unroll
        for (int p = 0; p < 2; p++) {
            int idx = tid + p * 256;
            int r = idx >> 2;
            int kq = (idx & 3) << 2;
            float4 av = *(const float4*)&g_rus[(size_t)(row0 + r) * HDIM + ks * 16 + kq];
            As[kq + 0][r] = av.x; As[kq + 1][r] = av.y; As[kq + 2][r] = av.z; As[kq + 3][r] = av.w;
        }
#pragma unroll
        for (int p = 0; p < 2; p++) {
            int idx = tid + p * 256;
            if (idx < 384) {
                int r = idx >> 2;
                int kq = (idx & 3) << 2;
                float4 wv = *(const float4*)&W[(size_t)(col0 + r) * CDIM + PDIM + ks * 16 + kq];
                Ws[kq + 0][r] = wv.x; Ws[kq + 1][r] = wv.y; Ws[kq + 2][r] = wv.z; Ws[kq + 3][r] = wv.w;
            }
        }
        __syncthreads();
#pragma unroll
        for (int kk = 0; kk < 16; kk++) {
            float4 a0 = *(const float4*)&As[kk][ty * 8];
            float4 a1 = *(const float4*)&As[kk][ty * 8 + 4];
            const unsigned long long* wp = (const unsigned long long*)&Ws[kk][tx * 6];
            unsigned long long wv0 = wp[0], wv1 = wp[1], wv2 = wp[2];
            float ar[8] = {a0.x, a0.y, a0.z, a0.w, a1.x, a1.y, a1.z, a1.w};
#pragma unroll
            for (int i = 0; i < 8; i++) {
                unsigned long long ad = pack2(ar[i], ar[i]);
                fma2(acc[i][0], ad, wv0);
                fma2(acc[i][1], ad, wv1);
                fma2(acc[i][2], ad, wv2);
            }
        }
        __syncthreads();
    }
    const int crow = row0 + ty * 8;
    const int ccol = col0 + tx * 6;
#pragma unroll
    for (int i = 0; i < 8; i++) {
        float2 p0 = unpack2(acc[i][0]), p1 = unpack2(acc[i][1]), p2 = unpack2(acc[i][2]);
        size_t base = (size_t)(crow + i) * HIDD + ccol;
        float2 h0 = *(float2*)&g_hid[base];
        float2 h1 = *(float2*)&g_hid[base + 2];
        float2 h2 = *(float2*)&g_hid[base + 4];
        *(float2*)&g_hid[base]     = make_float2(fmaxf(p0.x + h0.x, 0.f), fmaxf(p0.y + h0.y, 0.f));
        *(float2*)&g_hid[base + 2] = make_float2(fmaxf(p1.x + h1.x, 0.f), fmaxf(p1.y + h1.y, 0.f));
        *(float2*)&g_hid[base + 4] = make_float2(fmaxf(p2.x + h2.x, 0.f), fmaxf(p2.y + h2.y, 0.f));
    }
}

// ---------------- logits: out = g_hid @ w2[16,192]^T + b2 ----------------
__global__ __launch_bounds__(256) void k_logits(const float* __restrict__ w2,
                                                const float* __restrict__ b2,
                                                float* __restrict__ out) {
    __shared__ float sw[NEXPD * HIDD];
    __shared__ float sb[NEXPD];
    int tid = threadIdx.x;
    for (int idx = tid; idx < NEXPD * HIDD; idx += 256) sw[idx] = w2[idx];
    if (tid < NEXPD) sb[tid] = b2[tid];
    __syncthreads();
    int warp = tid >> 5, lane = tid & 31;
    size_t i = (size_t)blockIdx.x * 8 + warp;
    float h[6];
#pragma unroll
    for (int q = 0; q < 6; q++) h[q] = g_hid[i * HIDD + lane + 32 * q];
    float res = 0.f;
#pragma unroll
    for (int o = 0; o < NEXPD; o++) {
        float p = 0.f;
#pragma unroll
        for (int q = 0; q < 6; q++) p = fmaf(h[q], sw[o * HIDD + lane + 32 * q], p);
#pragma unroll
        for (int d = 16; d > 0; d >>= 1) p += __shfl_xor_sync(0xffffffffu, p, d);
        if (lane == o) res = p + sb[o];
    }
    if (lane < NEXPD) out[i * NEXPD + lane] = res;
}

// ---------------- launch ----------------
extern "C" void kernel_launch(void* const* d_in, const int* in_sizes, int n_in,
                              void* d_out, int out_size) {
    const float* te   = (const float*)d_in[0];
    const float* U    = (const float*)d_in[1];
    const float* R    = (const float*)d_in[2];
    const float* S    = (const float*)d_in[3];
    const float* tp_w = (const float*)d_in[4];
    const float* tp_b = (const float*)d_in[5];
    const float* q_w  = (const float*)d_in[6];
    const float* q_b  = (const float*)d_in[7];
    const float* k_w  = (const float*)d_in[8];
    const float* k_b  = (const float*)d_in[9];
    const float* v_w  = (const float*)d_in[10];
    const float* v_b  = (const float*)d_in[11];
    const float* wih  = (const float*)d_in[12];
    const float* whh  = (const float*)d_in[13];
    const float* bih  = (const float*)d_in[14];
    const float* bhh  = (const float*)d_in[15];
    const float* w1   = (const float*)d_in[16];
    const float* b1   = (const float*)d_in[17];
    const float* w2   = (const float*)d_in[18];
    const float* b2   = (const float*)d_in[19];
    float* out = (float*)d_out;

    k_pre<<<1, GDIM>>>(q_w, q_b, k_w, k_b, v_w, v_b, wih, bih);
    k_gemm1<<<dim3(NTOK / 128, PDIM / 128), 256>>>(te, tp_w, tp_b);
    k_attn<<<NTOK / 8, 256>>>(R, S);
    k_gru_mlp1a<<<NSEQ + MLPA_BLOCKS, GRU_THREADS>>>(U, whh, bhh, w1, b1);
    k_mlp1b<<<dim3(NTOK / 128, 2), 256>>>(w1);
    k_logits<<<NTOK / 8, 256>>>(w2, b2, out);
}